// round 2
// baseline (speedup 1.0000x reference)
#include <cuda_runtime.h>
#include <cuda_bf16.h>

#define N_USER 100000
#define N_ITEM 100000
#define N_NODES 200000
#define NNZ 6400000
#define EMB 64
#define BATCH 1024

// ---------------- scratch (device globals; no allocation allowed) ----------
__device__ int    g_rowptr[N_NODES + 1];
__device__ float  g_ego[2][(size_t)N_NODES * EMB];   // ping-pong ego buffers
__device__ float2 g_sp[(size_t)N_NODES * EMB];       // (side_k, prod_k) per (node,k)

// ---------------- 1) CSR row_ptr from sorted COO rows ----------------------
__global__ void build_rowptr(const int* __restrict__ row) {
    int r = blockIdx.x * blockDim.x + threadIdx.x;
    if (r > N_NODES) return;
    int lo = 0, hi = NNZ;                    // lower_bound: first i with row[i] >= r
    while (lo < hi) {
        int mid = (lo + hi) >> 1;
        if (row[mid] < r) lo = mid + 1; else hi = mid;
    }
    g_rowptr[r] = lo;
}

// ---------------- 2) ego0 = concat(user_emb, item_emb) ---------------------
__global__ void concat_ego(const float4* __restrict__ u, const float4* __restrict__ it) {
    int i = blockIdx.x * blockDim.x + threadIdx.x;
    const int NU4 = N_USER * EMB / 4;
    const int NT4 = N_NODES * EMB / 4;
    if (i >= NT4) return;
    float4 v = (i < NU4) ? u[i] : it[i - NU4];
    reinterpret_cast<float4*>(g_ego[0])[i] = v;
}

// ---------------- 3) output slice 0 (raw embeddings, gathered) -------------
__global__ void init_out(const int* __restrict__ users, const int* __restrict__ pos,
                         const int* __restrict__ neg,
                         const float* __restrict__ uemb, const float* __restrict__ iemb,
                         float* __restrict__ out) {
    int wid  = (blockIdx.x * blockDim.x + threadIdx.x) >> 5;
    int lane = threadIdx.x & 31;
    if (wid >= 3 * BATCH) return;
    int g = wid / BATCH, b = wid - g * BATCH;
    const float* src;
    if (g == 0)      src = uemb + (size_t)users[b] * EMB;
    else if (g == 1) src = iemb + (size_t)pos[b]   * EMB;
    else             src = iemb + (size_t)neg[b]   * EMB;
    float2 v = *reinterpret_cast<const float2*>(src + 2 * lane);
    *reinterpret_cast<float2*>(out + (size_t)wid * 256 + 2 * lane) = v;
}

// ---------------- 4) SpMM: side = A @ ego ; emit (side, ego*side) ----------
// warp per row; lane owns dim pair (2l, 2l+1)
__global__ void spmm_kernel(const int* __restrict__ col, const float* __restrict__ val,
                            int src) {
    __shared__ float2 stage[8][32];
    const float* __restrict__ ego = g_ego[src];
    int w = threadIdx.x >> 5, lane = threadIdx.x & 31;
    int r = blockIdx.x * 8 + w;
    if (r >= N_NODES) return;
    int beg = g_rowptr[r], end = g_rowptr[r + 1];
    float2 acc = make_float2(0.f, 0.f);
    for (int base = beg; base < end; base += 32) {
        int i = base + lane;
        if (i < end) stage[w][lane] = make_float2(val[i], __int_as_float(col[i]));
        __syncwarp();
        int cnt = min(32, end - base);
        #pragma unroll 4
        for (int j = 0; j < cnt; j++) {
            float2 cv = stage[w][j];
            int   c = __float_as_int(cv.y);
            float v = cv.x;
            float2 gx = *reinterpret_cast<const float2*>(ego + (size_t)c * EMB + 2 * lane);
            acc.x = fmaf(v, gx.x, acc.x);
            acc.y = fmaf(v, gx.y, acc.y);
        }
        __syncwarp();
    }
    float2 er = *reinterpret_cast<const float2*>(ego + (size_t)r * EMB + 2 * lane);
    float4 o;
    o.x = acc.x; o.y = er.x * acc.x;   // (s_{2l},  p_{2l})
    o.z = acc.y; o.w = er.y * acc.y;   // (s_{2l+1},p_{2l+1})
    *reinterpret_cast<float4*>(&g_sp[(size_t)r * EMB + 2 * lane]) = o;
}

// ---------------- 5) dense: ego_next = leaky(side@Wgc+bgc + prod@Wbi+bbi) --
// block = 64 rows; warp handles 8 rows; lane owns dim pair (2l, 2l+1);
// W register-blocked in k-chunks of 16 so smem traffic is broadcast-only.
__global__ void __launch_bounds__(256) dense_kernel(
        const float* __restrict__ Wgc, const float* __restrict__ bgc,
        const float* __restrict__ Wbi, const float* __restrict__ bbi,
        int dst) {
    __shared__ __align__(16) float2 sp_sh[64][EMB];   // 32 KB
    float* __restrict__ ego_next = g_ego[dst];
    int tid = threadIdx.x;
    int w = tid >> 5, lane = tid & 31;
    int rowbase = blockIdx.x * 64;

    // stage 64 rows of (s,p) pairs: 2048 float4, 8 per thread, coalesced
    const float4* src4 = reinterpret_cast<const float4*>(g_sp + (size_t)rowbase * EMB);
    float4* dst4 = reinterpret_cast<float4*>(sp_sh);
    #pragma unroll
    for (int i = 0; i < 8; i++) dst4[tid + i * 256] = src4[tid + i * 256];
    __syncthreads();

    float2 bg = *reinterpret_cast<const float2*>(bgc + 2 * lane);
    float2 bb = *reinterpret_cast<const float2*>(bbi + 2 * lane);

    const int r0 = w * 8;
    float2 accg[8], accb[8];
    #pragma unroll
    for (int r = 0; r < 8; r++) { accg[r] = make_float2(0.f, 0.f); accb[r] = make_float2(0.f, 0.f); }

    #pragma unroll
    for (int chunk = 0; chunk < 4; chunk++) {
        float2 wgc[16], wbi[16];
        #pragma unroll
        for (int t = 0; t < 16; t++) {
            int k = chunk * 16 + t;
            wgc[t] = *reinterpret_cast<const float2*>(Wgc + k * EMB + 2 * lane);
            wbi[t] = *reinterpret_cast<const float2*>(Wbi + k * EMB + 2 * lane);
        }
        #pragma unroll
        for (int r = 0; r < 8; r++) {
            #pragma unroll
            for (int t = 0; t < 16; t++) {
                float2 sp = sp_sh[r0 + r][chunk * 16 + t];   // broadcast LDS
                accg[r].x = fmaf(sp.x, wgc[t].x, accg[r].x);
                accg[r].y = fmaf(sp.x, wgc[t].y, accg[r].y);
                accb[r].x = fmaf(sp.y, wbi[t].x, accb[r].x);
                accb[r].y = fmaf(sp.y, wbi[t].y, accb[r].y);
            }
        }
    }
    #pragma unroll
    for (int r = 0; r < 8; r++) {
        float x = accg[r].x + bg.x + accb[r].x + bb.x;
        float y = accg[r].y + bg.y + accb[r].y + bb.y;
        x = x > 0.f ? x : 0.2f * x;
        y = y > 0.f ? y : 0.2f * y;
        *reinterpret_cast<float2*>(ego_next + (size_t)(rowbase + r0 + r) * EMB + 2 * lane)
            = make_float2(x, y);
    }
}

// ---------------- 6) per-layer gather + l2norm straight into d_out ---------
__global__ void gather_norm(const int* __restrict__ users, const int* __restrict__ pos,
                            const int* __restrict__ neg, int src, float* __restrict__ out,
                            int slice) {
    const float* __restrict__ ego = g_ego[src];
    int wid  = (blockIdx.x * blockDim.x + threadIdx.x) >> 5;
    int lane = threadIdx.x & 31;
    if (wid >= 3 * BATCH) return;
    int g = wid / BATCH, b = wid - g * BATCH;
    int node;
    if (g == 0)      node = users[b];
    else if (g == 1) node = N_USER + pos[b];
    else             node = N_USER + neg[b];
    float2 v = *reinterpret_cast<const float2*>(ego + (size_t)node * EMB + 2 * lane);
    float ss = v.x * v.x + v.y * v.y;
    #pragma unroll
    for (int o = 16; o; o >>= 1) ss += __shfl_xor_sync(0xffffffffu, ss, o);
    float n = sqrtf(ss);
    float inv = 1.f / fmaxf(n, 1e-12f);
    *reinterpret_cast<float2*>(out + (size_t)wid * 256 + slice * EMB + 2 * lane)
        = make_float2(v.x * inv, v.y * inv);
}

// ---------------- launch ---------------------------------------------------
extern "C" void kernel_launch(void* const* d_in, const int* in_sizes, int n_in,
                              void* d_out, int out_size) {
    const int*   users = (const int*)  d_in[0];
    const int*   pos   = (const int*)  d_in[1];
    const int*   neg   = (const int*)  d_in[2];
    const int*   arow  = (const int*)  d_in[3];
    const int*   acol  = (const int*)  d_in[4];
    const float* aval  = (const float*)d_in[5];
    const float* uemb  = (const float*)d_in[6];
    const float* iemb  = (const float*)d_in[7];
    const float* Wgc[3] = { (const float*)d_in[8],  (const float*)d_in[12], (const float*)d_in[16] };
    const float* bgc[3] = { (const float*)d_in[9],  (const float*)d_in[13], (const float*)d_in[17] };
    const float* Wbi[3] = { (const float*)d_in[10], (const float*)d_in[14], (const float*)d_in[18] };
    const float* bbi[3] = { (const float*)d_in[11], (const float*)d_in[15], (const float*)d_in[19] };
    float* out = (float*)d_out;

    build_rowptr<<<(N_NODES + 256) / 256, 256>>>(arow);
    concat_ego<<<(N_NODES * EMB / 4 + 255) / 256, 256>>>(
        (const float4*)uemb, (const float4*)iemb);
    init_out<<<(3 * BATCH * 32) / 256, 256>>>(users, pos, neg, uemb, iemb, out);

    int src = 0;
    for (int k = 0; k < 3; k++) {
        int dst = src ^ 1;
        spmm_kernel<<<N_NODES / 8, 256>>>(acol, aval, src);
        dense_kernel<<<N_NODES / 64, 256>>>(Wgc[k], bgc[k], Wbi[k], bbi[k], dst);
        gather_norm<<<(3 * BATCH * 32) / 256, 256>>>(users, pos, neg, dst, out, k + 1);
        src = dst;
    }
}